// round 15
// baseline (speedup 1.0000x reference)
#include <cuda_runtime.h>

#define LL 4096
#define CC 16
#define NB 16
#define OC 64
#define KS 7

#define NBLK_LOGICAL 2048     // logical tiles (= R12 grid)
#define NBLK_PERSIST 740      // 5 blocks/SM * 148 SMs

typedef unsigned long long u64;

__device__ __forceinline__ u64 pack2(float lo, float hi) {
    u64 r;
    asm("mov.b64 %0, {%1, %2};" : "=l"(r) : "f"(lo), "f"(hi));
    return r;
}
__device__ __forceinline__ u64 ffma2(u64 a, u64 b, u64 c) {
    u64 d;
    asm("fma.rn.f32x2 %0, %1, %2, %3;" : "=l"(d) : "l"(a), "l"(b), "l"(c));
    return d;
}
__device__ __forceinline__ u64 fmul2(u64 a, u64 b) {
    u64 d;
    asm("mul.rn.f32x2 %0, %1, %2;" : "=l"(d) : "l"(a), "l"(b));
    return d;
}
__device__ __forceinline__ void unpack2(u64 v, float& lo, float& hi) {
    asm("mov.b64 {%0, %1}, %2;" : "=f"(lo), "=f"(hi) : "l"(v));
}
// sigmoid(z) = 1/(1+exp(-z)) with minimal MUFU sequence.
__device__ __forceinline__ float fast_sigmoid(float z) {
    float e, r;
    asm("ex2.approx.f32 %0, %1;" : "=f"(e) : "f"(z * -1.442695041f));
    asm("rcp.approx.f32 %0, %1;" : "=f"(r) : "f"(1.f + e));
    return r;
}

__global__ __launch_bounds__(256, 5) void deform_conv_kernel(
    const float* __restrict__ x,
    const float* __restrict__ pw, const float* __restrict__ pb,
    const float* __restrict__ mw, const float* __restrict__ mb,
    const float* __restrict__ cw, const float* __restrict__ cb,
    float* __restrict__ out)
{
    // conv weights: [oc][8] scalar floats, taps 0-6 + bias in slot 7.
    __shared__ float s_w8[OC][8];
    // prep conv weights, lane-duplicated, packed per tap for LDS.128
    __shared__ ulonglong2 s_pA[KS], s_pB[KS], s_mA[KS], s_mB[KS];

    const int tid = threadIdx.x;
    for (int i = tid; i < OC * 8; i += blockDim.x) {
        const int oc = i >> 3, k = i & 7;
        s_w8[oc][k] = (k < KS) ? cw[oc * KS + k] : cb[oc];
    }
    if (tid < KS) {
        const float p0 = pw[tid * 3], p1 = pw[tid * 3 + 1], p2 = pw[tid * 3 + 2];
        const float m0 = mw[tid * 3], m1 = mw[tid * 3 + 1], m2 = mw[tid * 3 + 2];
        const float pbv = pb[tid], mbv = mb[tid];
        s_pA[tid] = make_ulonglong2(pack2(p0, p0), pack2(p1, p1));
        s_pB[tid] = make_ulonglong2(pack2(p2, p2), pack2(pbv, pbv));
        s_mA[tid] = make_ulonglong2(pack2(m0, m0), pack2(m1, m1));
        s_mB[tid] = make_ulonglong2(pack2(m2, m2), pack2(mbv, mbv));
    }
    __syncthreads();

    // persistent grid-stride over logical tiles: no wave-transition drain,
    // smem staging amortized over 2-3 tiles per block.
    for (int blk = blockIdx.x; blk < NBLK_LOGICAL; blk += NBLK_PERSIST) {
        const int t  = blk * 256 + tid;             // 2^19 logical threads
        const int c2 = t & 7;                       // channel pair (2 floats)
        const int l  = (t >> 3) & (LL - 1);
        const int b  = t >> 15;                     // 8*LL = 2^15 per batch

        const float* xb = x + b * (LL * CC);
        const float2* xb2 = (const float2*)xb;

        // 3-tap window over 2 channels (zero padding at edges, pad=1 conv)
        float2 sm1 = (l > 0)      ? __ldg(&xb2[(l - 1) * 8 + c2]) : make_float2(0.f, 0.f);
        float2 s0  =                __ldg(&xb2[l * 8 + c2]);
        float2 sp1 = (l < LL - 1) ? __ldg(&xb2[(l + 1) * 8 + c2]) : make_float2(0.f, 0.f);

        // channel-paired window values for f32x2 prep convs
        const u64 winp0 = pack2(sm1.x, sm1.y);
        const u64 winp1 = pack2(s0.x,  s0.y);
        const u64 winp2 = pack2(sp1.x, sp1.y);

        const float lf1 = (float)(l + 1);           // p_0 is 1-indexed

        float vk[2][KS];
        #pragma unroll
        for (int k = 0; k < KS; ++k) {
            // offset + mask convs, both channels at once (2x LDS.128 each)
            const ulonglong2 pA = s_pA[k], pB = s_pB[k];
            const ulonglong2 mA = s_mA[k], mB = s_mB[k];
            u64 off2 = ffma2(winp2, pB.x,
                       ffma2(winp1, pA.y,
                       ffma2(winp0, pA.x, pB.y)));
            u64 z2   = ffma2(winp2, mB.x,
                       ffma2(winp1, mA.y,
                       ffma2(winp0, mA.x, mB.y)));
            float offc[2], zc[2];
            unpack2(off2, offc[0], offc[1]);
            unpack2(z2,   zc[0],   zc[1]);

            const float pbase = lf1 + (float)(k - 3);
            #pragma unroll
            for (int i = 0; i < 2; ++i) {
                float m   = fast_sigmoid(zc[i]);
                float p   = pbase + offc[i];
                float qlt = fminf(fmaxf(floorf(p), 0.f), (float)(LL - 1));
                float qrb = fminf(qlt + 1.f, (float)(LL - 1));
                float pc  = fminf(fmaxf(p, 0.f), (float)(LL - 1));
                float glt = 1.f + (qlt - pc);
                float grb = 1.f - (qrb - pc);
                const int ch = c2 * 2 + i;
                float xlt = xb[(int)qlt * CC + ch];
                float xrb = xb[(int)qrb * CC + ch];
                vk[i][k] = (glt * xlt + grb * xrb) * m;
            }
        }

        // tap-paired packed v values (natural pairs, no duplication)
        u64 v01[2], v23[2], v45[2], v6b[2];
        #pragma unroll
        for (int i = 0; i < 2; ++i) {
            v01[i] = pack2(vk[i][0], vk[i][1]);
            v23[i] = pack2(vk[i][2], vk[i][3]);
            v45[i] = pack2(vk[i][4], vk[i][5]);
            v6b[i] = pack2(vk[i][6], 1.f);      // lane1 multiplies the bias
        }

        float2* out2 = (float2*)out;
        const int obase = ((b * OC) * LL + l) * 8 + c2;   // float2 index

        #pragma unroll 8
        for (int oc = 0; oc < OC; ++oc) {
            const ulonglong2* row = (const ulonglong2*)s_w8[oc];
            ulonglong2 wa = row[0];     // (w0,w1) (w2,w3)
            ulonglong2 wb = row[1];     // (w4,w5) (w6,bias)
            float r[2];
            #pragma unroll
            for (int i = 0; i < 2; ++i) {
                u64 acc = fmul2(v6b[i], wb.y);          // (w6*v6, bias)
                acc = ffma2(v01[i], wa.x, acc);
                acc = ffma2(v23[i], wa.y, acc);
                acc = ffma2(v45[i], wb.x, acc);
                float lo, hi;
                unpack2(acc, lo, hi);
                r[i] = lo + hi;
            }
            __stcs(&out2[obase + oc * (LL * 8)], make_float2(r[0], r[1]));
        }
    }
}

extern "C" void kernel_launch(void* const* d_in, const int* in_sizes, int n_in,
                              void* d_out, int out_size)
{
    const float* x  = (const float*)d_in[0];
    const float* pw = (const float*)d_in[1];
    const float* pb = (const float*)d_in[2];
    const float* mw = (const float*)d_in[3];
    const float* mb = (const float*)d_in[4];
    const float* cw = (const float*)d_in[5];
    const float* cb = (const float*)d_in[6];
    float* out = (float*)d_out;

    // persistent: 740 blocks (5/SM x 148 SMs), grid-stride over 2048 tiles
    deform_conv_kernel<<<NBLK_PERSIST, 256>>>(x, pw, pb, mw, mb, cw, cb, out);
}

// round 17
// speedup vs baseline: 1.1886x; 1.1886x over previous
#include <cuda_runtime.h>

#define LL 4096
#define CC 16
#define NB 16
#define OC 64
#define KS 7

typedef unsigned long long u64;

__device__ __forceinline__ u64 pack2(float lo, float hi) {
    u64 r;
    asm("mov.b64 %0, {%1, %2};" : "=l"(r) : "f"(lo), "f"(hi));
    return r;
}
__device__ __forceinline__ u64 ffma2(u64 a, u64 b, u64 c) {
    u64 d;
    asm("fma.rn.f32x2 %0, %1, %2, %3;" : "=l"(d) : "l"(a), "l"(b), "l"(c));
    return d;
}
__device__ __forceinline__ u64 fmul2(u64 a, u64 b) {
    u64 d;
    asm("mul.rn.f32x2 %0, %1, %2;" : "=l"(d) : "l"(a), "l"(b));
    return d;
}
__device__ __forceinline__ void unpack2(u64 v, float& lo, float& hi) {
    asm("mov.b64 {%0, %1}, %2;" : "=f"(lo), "=f"(hi) : "l"(v));
}
// sigmoid(z) = 1/(1+exp(-z)) with minimal MUFU sequence.
__device__ __forceinline__ float fast_sigmoid(float z) {
    float e, r;
    asm("ex2.approx.f32 %0, %1;" : "=f"(e) : "f"(z * -1.442695041f));
    asm("rcp.approx.f32 %0, %1;" : "=f"(r) : "f"(1.f + e));
    return r;
}

__global__ __launch_bounds__(256, 4) void deform_conv_kernel(
    const float* __restrict__ x,
    const float* __restrict__ pw, const float* __restrict__ pb,
    const float* __restrict__ mw, const float* __restrict__ mb,
    const float* __restrict__ cw, const float* __restrict__ cb,
    float* __restrict__ out)
{
    // conv weights: [oc][8] scalar floats, taps 0-6 + bias in slot 7.
    // Read in epilogue as u64 pairs: (w0,w1)(w2,w3)(w4,w5)(w6,bias).
    __shared__ float s_w8[OC][8];
    // prep conv weights, lane-duplicated, packed per tap for LDS.128
    __shared__ ulonglong2 s_pA[KS], s_pB[KS], s_mA[KS], s_mB[KS];

    const int tid = threadIdx.x;
    for (int i = tid; i < OC * 8; i += blockDim.x) {
        const int oc = i >> 3, k = i & 7;
        s_w8[oc][k] = (k < KS) ? cw[oc * KS + k] : cb[oc];
    }
    if (tid < KS) {
        const float p0 = pw[tid * 3], p1 = pw[tid * 3 + 1], p2 = pw[tid * 3 + 2];
        const float m0 = mw[tid * 3], m1 = mw[tid * 3 + 1], m2 = mw[tid * 3 + 2];
        const float pbv = pb[tid], mbv = mb[tid];
        s_pA[tid] = make_ulonglong2(pack2(p0, p0), pack2(p1, p1));
        s_pB[tid] = make_ulonglong2(pack2(p2, p2), pack2(pbv, pbv));
        s_mA[tid] = make_ulonglong2(pack2(m0, m0), pack2(m1, m1));
        s_mB[tid] = make_ulonglong2(pack2(m2, m2), pack2(mbv, mbv));
    }
    __syncthreads();

    const int t  = blockIdx.x * blockDim.x + tid;   // 2^19 threads total
    const int c2 = t & 7;                           // channel pair (2 floats)
    const int l  = (t >> 3) & (LL - 1);
    const int b  = t >> 15;                         // 8*LL = 2^15 per batch

    const float* xb = x + b * (LL * CC);
    const float2* xb2 = (const float2*)xb;

    // 3-tap window over 2 channels (zero padding at the edges, pad=1 conv)
    float2 sm1 = (l > 0)      ? __ldg(&xb2[(l - 1) * 8 + c2]) : make_float2(0.f, 0.f);
    float2 s0  =                __ldg(&xb2[l * 8 + c2]);
    float2 sp1 = (l < LL - 1) ? __ldg(&xb2[(l + 1) * 8 + c2]) : make_float2(0.f, 0.f);

    // channel-paired window values for f32x2 prep convs
    const u64 winp0 = pack2(sm1.x, sm1.y);
    const u64 winp1 = pack2(s0.x,  s0.y);
    const u64 winp2 = pack2(sp1.x, sp1.y);

    const float lf1 = (float)(l + 1);               // p_0 is 1-indexed

    float vk[2][KS];
    #pragma unroll
    for (int k = 0; k < KS; ++k) {
        // offset + mask convs, both channels at once (2x LDS.128 per conv)
        const ulonglong2 pA = s_pA[k], pB = s_pB[k];
        const ulonglong2 mA = s_mA[k], mB = s_mB[k];
        u64 off2 = ffma2(winp2, pB.x,
                   ffma2(winp1, pA.y,
                   ffma2(winp0, pA.x, pB.y)));
        u64 z2   = ffma2(winp2, mB.x,
                   ffma2(winp1, mA.y,
                   ffma2(winp0, mA.x, mB.y)));
        float offc[2], zc[2];
        unpack2(off2, offc[0], offc[1]);
        unpack2(z2,   zc[0],   zc[1]);

        const float pbase = lf1 + (float)(k - 3);   // single FADD, const folded
        #pragma unroll
        for (int i = 0; i < 2; ++i) {
            float m   = fast_sigmoid(zc[i]);
            float p   = pbase + offc[i];
            float qlt = fminf(fmaxf(floorf(p), 0.f), (float)(LL - 1));
            float qrb = fminf(qlt + 1.f, (float)(LL - 1));
            float pc  = fminf(fmaxf(p, 0.f), (float)(LL - 1));
            float glt = 1.f + (qlt - pc);
            float grb = 1.f - (qrb - pc);
            const int ch = c2 * 2 + i;
            float xlt = xb[(int)qlt * CC + ch];
            float xrb = xb[(int)qrb * CC + ch];
            vk[i][k] = (glt * xlt + grb * xrb) * m;
        }
    }

    // tap-paired packed v values (natural pairs, no duplication)
    u64 v01[2], v23[2], v45[2], v6b[2];
    #pragma unroll
    for (int i = 0; i < 2; ++i) {
        v01[i] = pack2(vk[i][0], vk[i][1]);
        v23[i] = pack2(vk[i][2], vk[i][3]);
        v45[i] = pack2(vk[i][4], vk[i][5]);
        v6b[i] = pack2(vk[i][6], 1.f);          // lane1 multiplies the bias
    }

    float2* out2 = (float2*)out;
    const int obase = ((b * OC) * LL + l) * 8 + c2;     // float2 index

    #pragma unroll 8
    for (int oc = 0; oc < OC; ++oc) {
        const ulonglong2* row = (const ulonglong2*)s_w8[oc];
        ulonglong2 wa = row[0];     // (w0,w1) (w2,w3)
        ulonglong2 wb = row[1];     // (w4,w5) (w6,bias)
        float r[2];
        #pragma unroll
        for (int i = 0; i < 2; ++i) {
            u64 acc = fmul2(v6b[i], wb.y);              // (w6*v6, bias)
            acc = ffma2(v01[i], wa.x, acc);
            acc = ffma2(v23[i], wa.y, acc);
            acc = ffma2(v45[i], wb.x, acc);
            float lo, hi;
            unpack2(acc, lo, hi);
            r[i] = lo + hi;
        }
        __stcs(&out2[obase + oc * (LL * 8)], make_float2(r[0], r[1]));
    }
}

extern "C" void kernel_launch(void* const* d_in, const int* in_sizes, int n_in,
                              void* d_out, int out_size)
{
    const float* x  = (const float*)d_in[0];
    const float* pw = (const float*)d_in[1];
    const float* pb = (const float*)d_in[2];
    const float* mw = (const float*)d_in[3];
    const float* mb = (const float*)d_in[4];
    const float* cw = (const float*)d_in[5];
    const float* cb = (const float*)d_in[6];
    float* out = (float*)d_out;

    // 16 batches * 4096 positions * 8 channel-pairs = 524288 threads
    deform_conv_kernel<<<2048, 256>>>(x, pw, pb, mw, mb, cw, cb, out);
}